// round 5
// baseline (speedup 1.0000x reference)
#include <cuda_runtime.h>
#include <cuda_bf16.h>
#include <cmath>

// Fractional LIF SNN.
//   Phase A: I_h[b*T+t, h] = data[b,t,:] . W_h[h,:] + b_h[h]
//            *** f32 sequential fmaf chain over k ascending *** per output
//            element — emulates cublas simt sgemm per-thread k-loop order,
//            which is what the reference (JAX->XLA->cuBLAS, full f32) ran.
//   Phase B: sequential Caputo-L1 recurrence, 1 block per batch item,
//            1 thread per hidden neuron, D-history in registers.
//   Memory weights: f32 powf (libdevice __nv_powf, matches XLA-GPU — verified
//   by output 0 becoming exactly 0 in round 3).
//   Memory sums: sequential ascending-s f32 fmaf chains.
//   I_o: fp64-exact warp reduction (held fixed this round to isolate I_h).

#define B_DIM   64
#define T_DIM   64
#define NIN     784
#define NHID    512
#define NOUT    10

// 8 MB scratch for precomputed hidden currents I[b*T+t][h]
__device__ float g_I[B_DIM * T_DIM * NHID];

// ---------------------------------------------------------------------------
// Chain GEMM: C[m,n] = seqchain_k( A[m,k]*W[n,k] ) + bias[n], f32 fmaf,
// k strictly ascending per output element (8 independent chains per thread
// for ILP). M=4096, K=784, N=512. Block tile 64(m) x 32(n), 256 threads.
// ---------------------------------------------------------------------------
#define CBK 16

__global__ void __launch_bounds__(256)
snn_gemm_chain(const float* __restrict__ A, const float* __restrict__ W,
               const float* __restrict__ bias, float* __restrict__ C) {
    __shared__ float As[CBK][65];   // [k][m], pad to kill store conflicts
    __shared__ float Ws[CBK][36];   // [k][n], rows 16B-aligned (36*4B)

    const int tid = threadIdx.x;
    const int m   = tid & 63;        // m within tile
    const int ng  = tid >> 6;        // n-group 0..3 (8 n each)
    const int m0  = blockIdx.x * 64;
    const int n0  = blockIdx.y * 32;

    const int arow = tid >> 2;           // 0..63
    const int akq  = (tid & 3) * 4;      // 0,4,8,12
    const int wrow = (tid & 127) >> 2;   // 0..31 (only tid<128 loads W)
    const int wkq  = (tid & 3) * 4;

    float acc[8] = {0.f,0.f,0.f,0.f,0.f,0.f,0.f,0.f};

    const int NKT = NIN / CBK;   // 49
    for (int kt = 0; kt < NKT; kt++) {
        const float4 ra =
            *(const float4*)&A[(size_t)(m0 + arow) * NIN + kt * CBK + akq];
        float4 rw = make_float4(0.f, 0.f, 0.f, 0.f);
        if (tid < 128)
            rw = *(const float4*)&W[(size_t)(n0 + wrow) * NIN + kt * CBK + wkq];
        __syncthreads();   // previous tile fully consumed
        As[akq + 0][arow] = ra.x; As[akq + 1][arow] = ra.y;
        As[akq + 2][arow] = ra.z; As[akq + 3][arow] = ra.w;
        if (tid < 128) {
            Ws[wkq + 0][wrow] = rw.x; Ws[wkq + 1][wrow] = rw.y;
            Ws[wkq + 2][wrow] = rw.z; Ws[wkq + 3][wrow] = rw.w;
        }
        __syncthreads();

#pragma unroll
        for (int k = 0; k < CBK; k++) {
            const float a  = As[k][m];
            const float4 w0 = *(const float4*)&Ws[k][ng * 8];
            const float4 w1 = *(const float4*)&Ws[k][ng * 8 + 4];
            // k strictly ascending within each acc chain (cublas simt order)
            acc[0] = fmaf(a, w0.x, acc[0]);
            acc[1] = fmaf(a, w0.y, acc[1]);
            acc[2] = fmaf(a, w0.z, acc[2]);
            acc[3] = fmaf(a, w0.w, acc[3]);
            acc[4] = fmaf(a, w1.x, acc[4]);
            acc[5] = fmaf(a, w1.y, acc[5]);
            acc[6] = fmaf(a, w1.z, acc[6]);
            acc[7] = fmaf(a, w1.w, acc[7]);
        }
    }

#pragma unroll
    for (int j = 0; j < 8; j++) {
        const int col = n0 + ng * 8 + j;
        C[(size_t)(m0 + m) * NHID + col] = __fadd_rn(acc[j], bias[col]);
    }
}

// ---------------------------------------------------------------------------
// Recurrence: one block per batch item. tid = hidden neuron. Warps 0..9 also
// own output neuron o = warp id.
// ---------------------------------------------------------------------------
__global__ void __launch_bounds__(512, 1)
snn_recur(const float* __restrict__ Wo, const float* __restrict__ bo,
          float* __restrict__ out, float scale) {
    const int b    = blockIdx.x;
    const int tid  = threadIdx.x;
    const int lane = tid & 31;
    const int wid  = tid >> 5;

    __shared__ float w_sh[T_DIM];
    __shared__ float spk_sh[2][NHID];
    __shared__ float Do_sh[NOUT][T_DIM];   // output-layer voltage-delta history

    if (tid < T_DIM) {
        // f32 powf == libdevice __nv_powf == XLA-GPU lowering (verified exact)
        const float lagf = (float)tid;
        w_sh[tid] = (tid >= 2)
                        ? (powf(lagf, 0.8f) - powf(lagf - 1.0f, 0.8f))
                        : 0.0f;
    }

    // output-layer weights in registers for warps 0..9
    float wo[16];
    float bo_r = 0.0f;
    if (wid < NOUT) {
#pragma unroll
        for (int j = 0; j < 16; j++) wo[j] = Wo[wid * NHID + lane + 32 * j];
        bo_r = bo[wid];
    }
    __syncthreads();

    float D[T_DIM];
    float V   = 0.0f;   // VRESET
    float Vo  = 0.0f;

    const float* Ibase = g_I + (size_t)(b * T_DIM) * NHID + tid;
    float Ibuf0 = Ibase[0];
    float Ibuf1 = Ibase[NHID];

    const float GLc = 0.025f;

#pragma unroll
    for (int t = 0; t < T_DIM; t++) {
        const float Icur = (t & 1) ? Ibuf1 : Ibuf0;
        if (t + 2 < T_DIM) {
            float v = Ibase[(size_t)(t + 2) * NHID];
            if (t & 1) Ibuf1 = v; else Ibuf0 = v;
        }

        // hidden memory: f32 sequential fmaf chain, s ascending
        float mem = 0.0f;
#pragma unroll
        for (int s = 0; s <= t - 2; s++)
            mem = fmaf(w_sh[t - s], D[s], mem);

        // Caputo L1 update, f32 ops in reference order (CM=0.5 -> *2 exact)
        const float f  = __fadd_rn(__fmul_rn(-GLc, V), Icur);
        const float g  = __fmul_rn(scale, f);
        const float h2 = __fmul_rn(g, 2.0f);
        const float Vn = __fsub_rn(__fadd_rn(V, h2), mem);
        const float spk = (Vn > 1.0f) ? 1.0f : 0.0f;
        const float Vp  = (Vn > 1.0f) ? 0.0f : Vn;
        D[t] = __fsub_rn(Vp, V);
        V = Vp;
        spk_sh[t & 1][tid] = spk;
        __syncthreads();

        if (wid < NOUT) {
            // I_o[o] = f32(sum_h spk[h]*W_o[o,h]) + b_o[o]  (fp64 warp reduce;
            // b_o is zeros so bias add is exact regardless of order)
            double p0 = 0.0, p1 = 0.0;
#pragma unroll
            for (int j = 0; j < 16; j += 2) {
                p0 = fma((double)spk_sh[t & 1][lane + 32 * j],       (double)wo[j],     p0);
                p1 = fma((double)spk_sh[t & 1][lane + 32 * (j + 1)], (double)wo[j + 1], p1);
            }
            double p = p0 + p1;
#pragma unroll
            for (int off = 16; off > 0; off >>= 1)
                p += __shfl_xor_sync(0xffffffffu, p, off);
            const float Io = __fadd_rn((float)p, bo_r);

            // output memory: f32 sequential fmaf chain, s ascending
            // (all lanes redundantly via broadcast smem reads)
            float mo = 0.0f;
#pragma unroll
            for (int s = 0; s <= t - 2; s++)
                mo = fmaf(w_sh[t - s], Do_sh[wid][s], mo);

            const float fo  = __fadd_rn(__fmul_rn(-GLc, Vo), Io);
            const float go  = __fmul_rn(scale, fo);
            const float ho  = __fmul_rn(go, 2.0f);
            const float Von = __fsub_rn(__fadd_rn(Vo, ho), mo);
            const float spko = (Von > 1.0f) ? 1.0f : 0.0f;
            const float Vop  = (Von > 1.0f) ? 0.0f : Von;
            const float dDo  = __fsub_rn(Vop, Vo);   // identical across lanes
            Vo = Vop;
            if (lane == 0) {
                Do_sh[wid][t] = dDo;   // read again only at t+2 (2 barriers away)
                const int idx = (t * B_DIM + b) * NOUT + wid;
                out[idx] = spko;                               // spk_trace [T,B,O]
                out[T_DIM * B_DIM * NOUT + idx] = Vo;          // mem_trace [T,B,O]
            }
        }
    }
}

// ---------------------------------------------------------------------------
extern "C" void kernel_launch(void* const* d_in, const int* in_sizes, int n_in,
                              void* d_out, int out_size) {
    const float* data = (const float*)d_in[0];   // [B,T,NIN]
    const float* W_h  = (const float*)d_in[1];   // [NHID,NIN]
    const float* b_h  = (const float*)d_in[2];   // [NHID]
    const float* W_o  = (const float*)d_in[3];   // [NOUT,NHID]
    const float* b_o  = (const float*)d_in[4];   // [NOUT]
    // d_in[5] = plotting (unused)

    float* I_ptr = nullptr;
    cudaGetSymbolAddress((void**)&I_ptr, g_I);   // no alloc; capture-safe

    const float scale = (float)(pow(0.1, 0.2) * tgamma(1.8));

    dim3 ggrid(B_DIM * T_DIM / 64, NHID / 32);   // (64, 16)
    snn_gemm_chain<<<ggrid, 256>>>(data, W_h, b_h, I_ptr);
    snn_recur<<<B_DIM, 512>>>(W_o, b_o, (float*)d_out, scale);
}

// round 6
// speedup vs baseline: 1.7858x; 1.7858x over previous
#include <cuda_runtime.h>
#include <cuda_bf16.h>
#include <cmath>

// Fractional LIF SNN — frozen numeric contract (validated R5, rel_err 2e-6):
//   * w_sh via f32 powf (libdevice __nv_powf, matches XLA-GPU)
//   * I_h: per-output single f32 accumulator, fmaf chain, k strictly ascending
//   * mem sums: ascending-s f32 fmaf chains
//   * I_o: fp64-exact warp reduce; elementwise ops in reference f32 order
// This round (bit-preserving optimizations only):
//   * GEMM: packed fma.rn.f32x2 (two independent IEEE f32 FMAs/instr; each
//     64-bit lane is exactly the scalar ascending-k chain) + 128x128x16
//     double-buffered tiling -> ~2x FMA throughput.
//   * recur: single __syncthreads per timestep (double-buffered spk_sh and
//     the t+1 barrier order all cross-iteration hazards).

#define B_DIM   64
#define T_DIM   64
#define NIN     784
#define NHID    512
#define NOUT    10

// 8 MB scratch for precomputed hidden currents I[b*T+t][h]
__device__ float g_I[B_DIM * T_DIM * NHID];

// ---------------------------------------------------------------------------
// packed f32x2 helpers
// ---------------------------------------------------------------------------
__device__ __forceinline__ unsigned long long ffma2(unsigned long long a,
                                                    unsigned long long b,
                                                    unsigned long long c) {
    unsigned long long d;
    asm("fma.rn.f32x2 %0, %1, %2, %3;" : "=l"(d) : "l"(a), "l"(b), "l"(c));
    return d;
}
__device__ __forceinline__ unsigned long long pack2(float x) {
    unsigned long long d;
    asm("mov.b64 %0, {%1, %1};" : "=l"(d) : "f"(x));
    return d;
}

// ---------------------------------------------------------------------------
// GEMM: C[m, n] = seqchain_k( A[m,k]*W[n,k] ) + bias[n]
// M = 4096, K = 784, N = 512.  Tiles: 128x128x16, 256 threads, 8x8 per thread
// (8 n-values as 4 packed f32x2).  Each output element is ONE f32 accumulator
// updated in strictly ascending k (kt outer asc, k inner asc) -> bit-identical
// to the scalar chain GEMM that passed in R5.
// ---------------------------------------------------------------------------
#define BM 128
#define BN 128
#define BK 16
#define PAD 4   // row stride BM+4 = 132 floats

__global__ void __launch_bounds__(256, 1)
snn_gemm(const float* __restrict__ A, const float* __restrict__ W,
         const float* __restrict__ bias, float* __restrict__ C) {
    __shared__ float As[2][BK][BM + PAD];
    __shared__ float Ws[2][BK][BN + PAD];

    const int tid = threadIdx.x;
    const int tx  = tid & 15;        // n-group 0..15
    const int ty  = tid >> 4;        // m-group 0..15
    const int m_blk = blockIdx.x * BM;
    const int n_blk = blockIdx.y * BN;

    const int row = tid >> 2;            // 0..63
    const int kq4 = (tid & 3) * 4;       // 0,4,8,12

    const float* Ap = A + (size_t)(m_blk + row) * NIN + kq4;
    const float* Wp = W + (size_t)(n_blk + row) * NIN + kq4;

    float4 ra0, ra1, rw0, rw1;

    // prologue: tile 0
    ra0 = *(const float4*)(Ap);
    ra1 = *(const float4*)(Ap + 64 * NIN);
    rw0 = *(const float4*)(Wp);
    rw1 = *(const float4*)(Wp + 64 * NIN);
    As[0][kq4 + 0][row] = ra0.x; As[0][kq4 + 1][row] = ra0.y;
    As[0][kq4 + 2][row] = ra0.z; As[0][kq4 + 3][row] = ra0.w;
    As[0][kq4 + 0][row + 64] = ra1.x; As[0][kq4 + 1][row + 64] = ra1.y;
    As[0][kq4 + 2][row + 64] = ra1.z; As[0][kq4 + 3][row + 64] = ra1.w;
    Ws[0][kq4 + 0][row] = rw0.x; Ws[0][kq4 + 1][row] = rw0.y;
    Ws[0][kq4 + 2][row] = rw0.z; Ws[0][kq4 + 3][row] = rw0.w;
    Ws[0][kq4 + 0][row + 64] = rw1.x; Ws[0][kq4 + 1][row + 64] = rw1.y;
    Ws[0][kq4 + 2][row + 64] = rw1.z; Ws[0][kq4 + 3][row + 64] = rw1.w;
    __syncthreads();

    unsigned long long acc[8][4];
#pragma unroll
    for (int m = 0; m < 8; m++)
#pragma unroll
        for (int j = 0; j < 4; j++) acc[m][j] = 0ULL;   // {+0.f, +0.f}

    const int NKT = NIN / BK;   // 49
    for (int kt = 0; kt < NKT; kt++) {
        const int cur = kt & 1;
        if (kt < NKT - 1) {
            const float* Ap2 = Ap + (kt + 1) * BK;
            const float* Wp2 = Wp + (kt + 1) * BK;
            ra0 = *(const float4*)(Ap2);
            ra1 = *(const float4*)(Ap2 + 64 * NIN);
            rw0 = *(const float4*)(Wp2);
            rw1 = *(const float4*)(Wp2 + 64 * NIN);
        }
#pragma unroll
        for (int k = 0; k < BK; k++) {
            const float4 a01 = *(const float4*)&As[cur][k][ty * 8];
            const float4 a23 = *(const float4*)&As[cur][k][ty * 8 + 4];
            unsigned long long b2[4];
#pragma unroll
            for (int j = 0; j < 4; j++)
                b2[j] = *(const unsigned long long*)&Ws[cur][k][2 * tx + 32 * j];
            const float av[8] = {a01.x, a01.y, a01.z, a01.w,
                                 a23.x, a23.y, a23.z, a23.w};
#pragma unroll
            for (int m = 0; m < 8; m++) {
                const unsigned long long a2 = pack2(av[m]);
#pragma unroll
                for (int j = 0; j < 4; j++)
                    acc[m][j] = ffma2(a2, b2[j], acc[m][j]);
            }
        }
        if (kt < NKT - 1) {
            const int nxt = cur ^ 1;
            As[nxt][kq4 + 0][row] = ra0.x; As[nxt][kq4 + 1][row] = ra0.y;
            As[nxt][kq4 + 2][row] = ra0.z; As[nxt][kq4 + 3][row] = ra0.w;
            As[nxt][kq4 + 0][row + 64] = ra1.x; As[nxt][kq4 + 1][row + 64] = ra1.y;
            As[nxt][kq4 + 2][row + 64] = ra1.z; As[nxt][kq4 + 3][row + 64] = ra1.w;
            Ws[nxt][kq4 + 0][row] = rw0.x; Ws[nxt][kq4 + 1][row] = rw0.y;
            Ws[nxt][kq4 + 2][row] = rw0.z; Ws[nxt][kq4 + 3][row] = rw0.w;
            Ws[nxt][kq4 + 0][row + 64] = rw1.x; Ws[nxt][kq4 + 1][row + 64] = rw1.y;
            Ws[nxt][kq4 + 2][row + 64] = rw1.z; Ws[nxt][kq4 + 3][row + 64] = rw1.w;
            __syncthreads();
        }
    }

    // epilogue: add bias, store float2 (lo lane -> col, hi lane -> col+1)
#pragma unroll
    for (int m = 0; m < 8; m++) {
        const int gm = m_blk + ty * 8 + m;
#pragma unroll
        for (int j = 0; j < 4; j++) {
            const int col = n_blk + 2 * tx + 32 * j;
            const unsigned long long v = acc[m][j];
            const float lo = __uint_as_float((unsigned)(v & 0xffffffffu));
            const float hi = __uint_as_float((unsigned)(v >> 32));
            float2 o;
            o.x = __fadd_rn(lo, bias[col]);
            o.y = __fadd_rn(hi, bias[col + 1]);
            *(float2*)&C[(size_t)gm * NHID + col] = o;
        }
    }
}

// ---------------------------------------------------------------------------
// Recurrence: one block per batch item. tid = hidden neuron. Warps 0..9 also
// own output neuron o = warp id.  ONE __syncthreads per timestep:
//   spk_sh is double-buffered (overwrite at t+2 is ordered by t+1's barrier);
//   Do_sh[wid][t] write (iter t) -> read (iter >= t+2) ordered by t+1 barrier.
// ---------------------------------------------------------------------------
__global__ void __launch_bounds__(512, 1)
snn_recur(const float* __restrict__ Wo, const float* __restrict__ bo,
          float* __restrict__ out, float scale) {
    const int b    = blockIdx.x;
    const int tid  = threadIdx.x;
    const int lane = tid & 31;
    const int wid  = tid >> 5;

    __shared__ float w_sh[T_DIM];
    __shared__ float spk_sh[2][NHID];
    __shared__ float Do_sh[NOUT][T_DIM];   // output-layer voltage-delta history

    if (tid < T_DIM) {
        // f32 powf == libdevice __nv_powf == XLA-GPU lowering (verified exact)
        const float lagf = (float)tid;
        w_sh[tid] = (tid >= 2)
                        ? (powf(lagf, 0.8f) - powf(lagf - 1.0f, 0.8f))
                        : 0.0f;
    }

    // output-layer weights in registers for warps 0..9
    float wo[16];
    float bo_r = 0.0f;
    if (wid < NOUT) {
#pragma unroll
        for (int j = 0; j < 16; j++) wo[j] = Wo[wid * NHID + lane + 32 * j];
        bo_r = bo[wid];
    }
    __syncthreads();

    float D[T_DIM];
    float V   = 0.0f;   // VRESET
    float Vo  = 0.0f;

    const float* Ibase = g_I + (size_t)(b * T_DIM) * NHID + tid;
    float Ibuf0 = Ibase[0];
    float Ibuf1 = Ibase[NHID];

    const float GLc = 0.025f;

#pragma unroll
    for (int t = 0; t < T_DIM; t++) {
        const float Icur = (t & 1) ? Ibuf1 : Ibuf0;
        if (t + 2 < T_DIM) {
            float v = Ibase[(size_t)(t + 2) * NHID];
            if (t & 1) Ibuf1 = v; else Ibuf0 = v;
        }

        // hidden memory: f32 sequential fmaf chain, s ascending
        float mem = 0.0f;
#pragma unroll
        for (int s = 0; s <= t - 2; s++)
            mem = fmaf(w_sh[t - s], D[s], mem);

        // Caputo L1 update, f32 ops in reference order (CM=0.5 -> *2 exact)
        const float f  = __fadd_rn(__fmul_rn(-GLc, V), Icur);
        const float g  = __fmul_rn(scale, f);
        const float h2 = __fmul_rn(g, 2.0f);
        const float Vn = __fsub_rn(__fadd_rn(V, h2), mem);
        const float spk = (Vn > 1.0f) ? 1.0f : 0.0f;
        const float Vp  = (Vn > 1.0f) ? 0.0f : Vn;
        D[t] = __fsub_rn(Vp, V);
        V = Vp;
        spk_sh[t & 1][tid] = spk;
        __syncthreads();   // the ONLY barrier per timestep

        if (wid < NOUT) {
            // I_o[o] = f32(sum_h spk[h]*W_o[o,h]) + b_o[o]  (fp64 warp reduce;
            // b_o is zeros so bias add is exact regardless of order)
            double p0 = 0.0, p1 = 0.0;
#pragma unroll
            for (int j = 0; j < 16; j += 2) {
                p0 = fma((double)spk_sh[t & 1][lane + 32 * j],       (double)wo[j],     p0);
                p1 = fma((double)spk_sh[t & 1][lane + 32 * (j + 1)], (double)wo[j + 1], p1);
            }
            double p = p0 + p1;
#pragma unroll
            for (int off = 16; off > 0; off >>= 1)
                p += __shfl_xor_sync(0xffffffffu, p, off);
            const float Io = __fadd_rn((float)p, bo_r);

            // output memory: f32 sequential fmaf chain, s ascending
            // (all lanes redundantly via broadcast smem reads)
            float mo = 0.0f;
#pragma unroll
            for (int s = 0; s <= t - 2; s++)
                mo = fmaf(w_sh[t - s], Do_sh[wid][s], mo);

            const float fo  = __fadd_rn(__fmul_rn(-GLc, Vo), Io);
            const float go  = __fmul_rn(scale, fo);
            const float ho  = __fmul_rn(go, 2.0f);
            const float Von = __fsub_rn(__fadd_rn(Vo, ho), mo);
            const float spko = (Von > 1.0f) ? 1.0f : 0.0f;
            const float Vop  = (Von > 1.0f) ? 0.0f : Von;
            const float dDo  = __fsub_rn(Vop, Vo);   // identical across lanes
            Vo = Vop;
            if (lane == 0) {
                Do_sh[wid][t] = dDo;   // first read at t+2, past t+1's barrier
                const int idx = (t * B_DIM + b) * NOUT + wid;
                out[idx] = spko;                               // spk_trace [T,B,O]
                out[T_DIM * B_DIM * NOUT + idx] = Vo;          // mem_trace [T,B,O]
            }
        }
    }
}

// ---------------------------------------------------------------------------
extern "C" void kernel_launch(void* const* d_in, const int* in_sizes, int n_in,
                              void* d_out, int out_size) {
    const float* data = (const float*)d_in[0];   // [B,T,NIN]
    const float* W_h  = (const float*)d_in[1];   // [NHID,NIN]
    const float* b_h  = (const float*)d_in[2];   // [NHID]
    const float* W_o  = (const float*)d_in[3];   // [NOUT,NHID]
    const float* b_o  = (const float*)d_in[4];   // [NOUT]
    // d_in[5] = plotting (unused)

    float* I_ptr = nullptr;
    cudaGetSymbolAddress((void**)&I_ptr, g_I);   // no alloc; capture-safe

    const float scale = (float)(pow(0.1, 0.2) * tgamma(1.8));

    dim3 ggrid(B_DIM * T_DIM / BM, NHID / BN);   // (32, 4)
    snn_gemm<<<ggrid, 256>>>(data, W_h, b_h, I_ptr);
    snn_recur<<<B_DIM, 512>>>(W_o, b_o, (float*)d_out, scale);
}

// round 7
// speedup vs baseline: 2.1605x; 1.2098x over previous
#include <cuda_runtime.h>
#include <cuda_bf16.h>
#include <cmath>

// Fractional LIF SNN — frozen numeric contract (validated R5/R6, rel_err 2e-6):
//   * w_sh via f32 powf (libdevice __nv_powf, matches XLA-GPU)
//   * I_h: per-output single f32 accumulator, fmaf chain, k strictly ascending
//     (implemented with fma.rn.f32x2: each 64-bit lane is exactly that chain)
//   * mem sums: ascending-s f32 fmaf chains (hidden AND output)
//   * I_o: fp64-exact sum, round once, f32 bias add
//   * elementwise recurrence ops in reference f32 order
// R7 structure: GEMM (unchanged) + ONE fused recurrence kernel:
//   phase 1: hidden recurrence with NO barriers, spikes exported as ballot
//            bitmasks (output layer only needs bits);
//   phase 2: all 640 I_o dots (fp64 selective sums from bitmasks, W_o in smem);
//   phase 3: output recurrence, 10 threads, Do history in registers.

#define B_DIM   64
#define T_DIM   64
#define NIN     784
#define NHID    512
#define NOUT    10

// 8 MB scratch for precomputed hidden currents I[b*T+t][h]
__device__ float g_I[B_DIM * T_DIM * NHID];

// ---------------------------------------------------------------------------
// packed f32x2 helpers
// ---------------------------------------------------------------------------
__device__ __forceinline__ unsigned long long ffma2(unsigned long long a,
                                                    unsigned long long b,
                                                    unsigned long long c) {
    unsigned long long d;
    asm("fma.rn.f32x2 %0, %1, %2, %3;" : "=l"(d) : "l"(a), "l"(b), "l"(c));
    return d;
}
__device__ __forceinline__ unsigned long long pack2(float x) {
    unsigned long long d;
    asm("mov.b64 %0, {%1, %1};" : "=l"(d) : "f"(x));
    return d;
}

// ---------------------------------------------------------------------------
// GEMM: C[m, n] = seqchain_k( A[m,k]*W[n,k] ) + bias[n]
// M = 4096, K = 784, N = 512.  128x128x16 double-buffered, 256 threads,
// 8x8 per thread as 4 packed f32x2. Bit-identical to scalar ascending chain.
// ---------------------------------------------------------------------------
#define BM 128
#define BN 128
#define BK 16
#define PAD 4

__global__ void __launch_bounds__(256, 1)
snn_gemm(const float* __restrict__ A, const float* __restrict__ W,
         const float* __restrict__ bias, float* __restrict__ C) {
    __shared__ float As[2][BK][BM + PAD];
    __shared__ float Ws[2][BK][BN + PAD];

    const int tid = threadIdx.x;
    const int tx  = tid & 15;
    const int ty  = tid >> 4;
    const int m_blk = blockIdx.x * BM;
    const int n_blk = blockIdx.y * BN;

    const int row = tid >> 2;
    const int kq4 = (tid & 3) * 4;

    const float* Ap = A + (size_t)(m_blk + row) * NIN + kq4;
    const float* Wp = W + (size_t)(n_blk + row) * NIN + kq4;

    float4 ra0, ra1, rw0, rw1;

    ra0 = *(const float4*)(Ap);
    ra1 = *(const float4*)(Ap + 64 * NIN);
    rw0 = *(const float4*)(Wp);
    rw1 = *(const float4*)(Wp + 64 * NIN);
    As[0][kq4 + 0][row] = ra0.x; As[0][kq4 + 1][row] = ra0.y;
    As[0][kq4 + 2][row] = ra0.z; As[0][kq4 + 3][row] = ra0.w;
    As[0][kq4 + 0][row + 64] = ra1.x; As[0][kq4 + 1][row + 64] = ra1.y;
    As[0][kq4 + 2][row + 64] = ra1.z; As[0][kq4 + 3][row + 64] = ra1.w;
    Ws[0][kq4 + 0][row] = rw0.x; Ws[0][kq4 + 1][row] = rw0.y;
    Ws[0][kq4 + 2][row] = rw0.z; Ws[0][kq4 + 3][row] = rw0.w;
    Ws[0][kq4 + 0][row + 64] = rw1.x; Ws[0][kq4 + 1][row + 64] = rw1.y;
    Ws[0][kq4 + 2][row + 64] = rw1.z; Ws[0][kq4 + 3][row + 64] = rw1.w;
    __syncthreads();

    unsigned long long acc[8][4];
#pragma unroll
    for (int m = 0; m < 8; m++)
#pragma unroll
        for (int j = 0; j < 4; j++) acc[m][j] = 0ULL;

    const int NKT = NIN / BK;   // 49
    for (int kt = 0; kt < NKT; kt++) {
        const int cur = kt & 1;
        if (kt < NKT - 1) {
            const float* Ap2 = Ap + (kt + 1) * BK;
            const float* Wp2 = Wp + (kt + 1) * BK;
            ra0 = *(const float4*)(Ap2);
            ra1 = *(const float4*)(Ap2 + 64 * NIN);
            rw0 = *(const float4*)(Wp2);
            rw1 = *(const float4*)(Wp2 + 64 * NIN);
        }
#pragma unroll
        for (int k = 0; k < BK; k++) {
            const float4 a01 = *(const float4*)&As[cur][k][ty * 8];
            const float4 a23 = *(const float4*)&As[cur][k][ty * 8 + 4];
            unsigned long long b2[4];
#pragma unroll
            for (int j = 0; j < 4; j++)
                b2[j] = *(const unsigned long long*)&Ws[cur][k][2 * tx + 32 * j];
            const float av[8] = {a01.x, a01.y, a01.z, a01.w,
                                 a23.x, a23.y, a23.z, a23.w};
#pragma unroll
            for (int m = 0; m < 8; m++) {
                const unsigned long long a2 = pack2(av[m]);
#pragma unroll
                for (int j = 0; j < 4; j++)
                    acc[m][j] = ffma2(a2, b2[j], acc[m][j]);
            }
        }
        if (kt < NKT - 1) {
            const int nxt = cur ^ 1;
            As[nxt][kq4 + 0][row] = ra0.x; As[nxt][kq4 + 1][row] = ra0.y;
            As[nxt][kq4 + 2][row] = ra0.z; As[nxt][kq4 + 3][row] = ra0.w;
            As[nxt][kq4 + 0][row + 64] = ra1.x; As[nxt][kq4 + 1][row + 64] = ra1.y;
            As[nxt][kq4 + 2][row + 64] = ra1.z; As[nxt][kq4 + 3][row + 64] = ra1.w;
            Ws[nxt][kq4 + 0][row] = rw0.x; Ws[nxt][kq4 + 1][row] = rw0.y;
            Ws[nxt][kq4 + 2][row] = rw0.z; Ws[nxt][kq4 + 3][row] = rw0.w;
            Ws[nxt][kq4 + 0][row + 64] = rw1.x; Ws[nxt][kq4 + 1][row + 64] = rw1.y;
            Ws[nxt][kq4 + 2][row + 64] = rw1.z; Ws[nxt][kq4 + 3][row + 64] = rw1.w;
            __syncthreads();
        }
    }

#pragma unroll
    for (int m = 0; m < 8; m++) {
        const int gm = m_blk + ty * 8 + m;
#pragma unroll
        for (int j = 0; j < 4; j++) {
            const int col = n_blk + 2 * tx + 32 * j;
            const unsigned long long v = acc[m][j];
            const float lo = __uint_as_float((unsigned)(v & 0xffffffffu));
            const float hi = __uint_as_float((unsigned)(v >> 32));
            float2 o;
            o.x = __fadd_rn(lo, bias[col]);
            o.y = __fadd_rn(hi, bias[col + 1]);
            *(float2*)&C[(size_t)gm * NHID + col] = o;
        }
    }
}

// ---------------------------------------------------------------------------
// Fused recurrence: one block per batch item, 512 threads.
// ---------------------------------------------------------------------------
__global__ void __launch_bounds__(512, 1)
snn_recur_fused(const float* __restrict__ Wo, const float* __restrict__ bo,
                float* __restrict__ out, float scale) {
    const int b    = blockIdx.x;
    const int tid  = threadIdx.x;
    const int lane = tid & 31;
    const int wid  = tid >> 5;

    __shared__ float    w_sh[T_DIM];
    __shared__ unsigned spkmask[T_DIM][16];      // hidden spike bits per warp
    __shared__ float    Wo_sh[NOUT][NHID];       // 20 KB
    __shared__ float    Io_sh[T_DIM][NOUT];      // 2.5 KB

    if (tid < T_DIM) {
        // f32 powf == libdevice __nv_powf == XLA-GPU lowering (verified exact)
        const float lagf = (float)tid;
        w_sh[tid] = (tid >= 2)
                        ? (powf(lagf, 0.8f) - powf(lagf - 1.0f, 0.8f))
                        : 0.0f;
    }
    for (int i = tid; i < NOUT * NHID; i += 512)
        Wo_sh[i / NHID][i % NHID] = Wo[i];
    __syncthreads();

    // ---------------- phase 1: hidden recurrence (no barriers) -------------
    {
        float D[T_DIM];
        float V = 0.0f;   // VRESET
        const float* Ibase = g_I + (size_t)(b * T_DIM) * NHID + tid;
        float Ibuf0 = Ibase[0];
        float Ibuf1 = Ibase[NHID];
        const float GLc = 0.025f;

#pragma unroll
        for (int t = 0; t < T_DIM; t++) {
            const float Icur = (t & 1) ? Ibuf1 : Ibuf0;
            if (t + 2 < T_DIM) {
                float v = Ibase[(size_t)(t + 2) * NHID];
                if (t & 1) Ibuf1 = v; else Ibuf0 = v;
            }

            // hidden memory: f32 sequential fmaf chain, s ascending (frozen)
            float mem = 0.0f;
#pragma unroll
            for (int s = 0; s <= t - 2; s++)
                mem = fmaf(w_sh[t - s], D[s], mem);

            // Caputo L1 update, f32 ops in reference order
            const float f  = __fadd_rn(__fmul_rn(-GLc, V), Icur);
            const float g  = __fmul_rn(scale, f);
            const float h2 = __fmul_rn(g, 2.0f);
            const float Vn = __fsub_rn(__fadd_rn(V, h2), mem);
            const float Vp = (Vn > 1.0f) ? 0.0f : Vn;
            D[t] = __fsub_rn(Vp, V);
            V = Vp;

            const unsigned msk = __ballot_sync(0xffffffffu, Vn > 1.0f);
            if (lane == 0) spkmask[t][wid] = msk;
        }
    }
    __syncthreads();

    // ---------------- phase 2: all 640 I_o dots (fp64-exact) ---------------
    // warp w handles (t,o) pairs idx = w, w+16, ... (40 per warp)
    for (int idx = wid; idx < T_DIM * NOUT; idx += 16) {
        const int t = idx / NOUT;
        const int o = idx - t * NOUT;
        double s0 = 0.0, s1 = 0.0, s2 = 0.0, s3 = 0.0;
#pragma unroll
        for (int j = 0; j < 16; j += 4) {
            const unsigned m0 = spkmask[t][j + 0];
            const unsigned m1 = spkmask[t][j + 1];
            const unsigned m2 = spkmask[t][j + 2];
            const unsigned m3 = spkmask[t][j + 3];
            if ((m0 >> lane) & 1u) s0 += (double)Wo_sh[o][(j + 0) * 32 + lane];
            if ((m1 >> lane) & 1u) s1 += (double)Wo_sh[o][(j + 1) * 32 + lane];
            if ((m2 >> lane) & 1u) s2 += (double)Wo_sh[o][(j + 2) * 32 + lane];
            if ((m3 >> lane) & 1u) s3 += (double)Wo_sh[o][(j + 3) * 32 + lane];
        }
        double p = (s0 + s1) + (s2 + s3);
#pragma unroll
        for (int off = 16; off > 0; off >>= 1)
            p += __shfl_xor_sync(0xffffffffu, p, off);
        if (lane == 0)
            Io_sh[t][o] = __fadd_rn((float)p, bo[o]);
    }
    __syncthreads();

    // ---------------- phase 3: output recurrence (10 threads) --------------
    if (tid < NOUT) {
        const int o = tid;
        float Do[T_DIM];
        float Vo = 0.0f;
        const float GLc = 0.025f;

#pragma unroll
        for (int t = 0; t < T_DIM; t++) {
            // output memory: f32 sequential fmaf chain, s ascending (frozen)
            float mo = 0.0f;
#pragma unroll
            for (int s = 0; s <= t - 2; s++)
                mo = fmaf(w_sh[t - s], Do[s], mo);

            const float Io  = Io_sh[t][o];
            const float fo  = __fadd_rn(__fmul_rn(-GLc, Vo), Io);
            const float go  = __fmul_rn(scale, fo);
            const float ho  = __fmul_rn(go, 2.0f);
            const float Von = __fsub_rn(__fadd_rn(Vo, ho), mo);
            const float spko = (Von > 1.0f) ? 1.0f : 0.0f;
            const float Vop  = (Von > 1.0f) ? 0.0f : Von;
            Do[t] = __fsub_rn(Vop, Vo);
            Vo = Vop;

            const int idx = (t * B_DIM + b) * NOUT + o;
            out[idx] = spko;                               // spk_trace [T,B,O]
            out[T_DIM * B_DIM * NOUT + idx] = Vo;          // mem_trace [T,B,O]
        }
    }
}

// ---------------------------------------------------------------------------
extern "C" void kernel_launch(void* const* d_in, const int* in_sizes, int n_in,
                              void* d_out, int out_size) {
    const float* data = (const float*)d_in[0];   // [B,T,NIN]
    const float* W_h  = (const float*)d_in[1];   // [NHID,NIN]
    const float* b_h  = (const float*)d_in[2];   // [NHID]
    const float* W_o  = (const float*)d_in[3];   // [NOUT,NHID]
    const float* b_o  = (const float*)d_in[4];   // [NOUT]
    // d_in[5] = plotting (unused)

    float* I_ptr = nullptr;
    cudaGetSymbolAddress((void**)&I_ptr, g_I);   // no alloc; capture-safe

    const float scale = (float)(pow(0.1, 0.2) * tgamma(1.8));

    dim3 ggrid(B_DIM * T_DIM / BM, NHID / BN);   // (32, 4)
    snn_gemm<<<ggrid, 256>>>(data, W_h, b_h, I_ptr);
    snn_recur_fused<<<B_DIM, 512>>>(W_o, b_o, (float*)d_out, scale);
}